// round 1
// baseline (speedup 1.0000x reference)
#include <cuda_runtime.h>
#include <math.h>

#define LATENT 256
#define HID 512
#define NT 16
#define MAXB 2048

// scratch (allocation-free rule: device globals)
__device__ float g_h[MAXB * HID];
__device__ float g_e1[MAXB * HID];

// ---------------------------------------------------------------------------
// Register-blocked SGEMM: C[M,N] = act(A[M,K] @ (B0 (+ B1)) + bias)
// BM=32, BN=64, BK=16, 128 threads, 4x4 microtile per thread.
// SUM_B folds the cat(h,h)@W_e1 into one pass: B = W_e1_top + W_e1_bottom.
// ---------------------------------------------------------------------------
template<bool SUM_B, bool RELU>
__global__ __launch_bounds__(128)
void gemm_tiled(const float* __restrict__ A,
                const float* __restrict__ B0,
                const float* __restrict__ B1,
                const float* __restrict__ bias,
                float* __restrict__ C,
                int M, int N, int K)
{
    constexpr int BM = 32, BN = 64, BK = 16;
    __shared__ float As[BK][BM];
    __shared__ float Bs[BK][BN];

    const int tx = threadIdx.x;
    const int rowBase = blockIdx.y * BM;
    const int colBase = blockIdx.x * BN;

    // loader indices
    const int arow = tx >> 2;          // 0..31
    const int acol = (tx & 3) << 2;    // 0,4,8,12
    const int brw  = tx >> 4;          // 0..7
    const int bcl  = (tx & 15) << 2;   // 0..60

    // compute indices
    const int tm0 = (tx >> 4) << 2;    // 0..28
    const int tn0 = (tx & 15) << 2;    // 0..60

    float acc[4][4] = {};

    for (int k0 = 0; k0 < K; k0 += BK) {
        // A tile (BMxBK), store transposed for coalesced smem reads
        float4 av = make_float4(0.f, 0.f, 0.f, 0.f);
        int gr = rowBase + arow;
        if (gr < M)
            av = *reinterpret_cast<const float4*>(A + (size_t)gr * K + k0 + acol);
        As[acol + 0][arow] = av.x;
        As[acol + 1][arow] = av.y;
        As[acol + 2][arow] = av.z;
        As[acol + 3][arow] = av.w;

        // B tile (BKxBN), two rows per thread, optional B1 add on load
        #pragma unroll
        for (int r = 0; r < 2; r++) {
            int kr = brw + r * 8;
            float4 bv = *reinterpret_cast<const float4*>(
                B0 + (size_t)(k0 + kr) * N + colBase + bcl);
            if (SUM_B) {
                float4 b1 = *reinterpret_cast<const float4*>(
                    B1 + (size_t)(k0 + kr) * N + colBase + bcl);
                bv.x += b1.x; bv.y += b1.y; bv.z += b1.z; bv.w += b1.w;
            }
            *reinterpret_cast<float4*>(&Bs[kr][bcl]) = bv;
        }
        __syncthreads();

        #pragma unroll
        for (int kk = 0; kk < BK; kk++) {
            float4 a = *reinterpret_cast<const float4*>(&As[kk][tm0]);
            float4 b = *reinterpret_cast<const float4*>(&Bs[kk][tn0]);
            float ar[4] = {a.x, a.y, a.z, a.w};
            float br[4] = {b.x, b.y, b.z, b.w};
            #pragma unroll
            for (int i = 0; i < 4; i++)
                #pragma unroll
                for (int j = 0; j < 4; j++)
                    acc[i][j] = fmaf(ar[i], br[j], acc[i][j]);
        }
        __syncthreads();
    }

    float4 bb = *reinterpret_cast<const float4*>(bias + colBase + tn0);
    float bbr[4] = {bb.x, bb.y, bb.z, bb.w};
    #pragma unroll
    for (int i = 0; i < 4; i++) {
        int r = rowBase + tm0 + i;
        if (r < M) {
            float4 v;
            float* vp = &v.x;
            #pragma unroll
            for (int j = 0; j < 4; j++) {
                float x = acc[i][j] + bbr[j];
                if (RELU) x = fmaxf(x, 0.f);
                vp[j] = x;
            }
            *reinterpret_cast<float4*>(C + (size_t)r * N + colBase + tn0) = v;
        }
    }
}

// ---------------------------------------------------------------------------
// Finalize: one block per batch row b.
//   logits[t] = h[b] . W_node[:,t] + b_node[t]      (16-wide GEMV)
//   p         = sigmoid(e1[b] . W_e2 + b_e2)
//   out[0 : B*N*16)              = logits broadcast over N
//   out[B*N*16 : B*N*16 + B*N*N) = p * strict-lower-tri mask
// ---------------------------------------------------------------------------
__global__ __launch_bounds__(256)
void finalize_kernel(const float* __restrict__ g_h_p,
                     const float* __restrict__ g_e1_p,
                     const float* __restrict__ W_node,
                     const float* __restrict__ b_node,
                     const float* __restrict__ W_e2,
                     const float* __restrict__ b_e2,
                     float* __restrict__ out,
                     int Bsz, int N, int has_edges)
{
    const int b = blockIdx.x;
    const int tid = threadIdx.x;
    __shared__ float sh_h[HID];
    __shared__ float sh_logits[NT];
    __shared__ float sred[256];
    __shared__ float sh_p;

    for (int k = tid; k < HID; k += 256) sh_h[k] = g_h_p[(size_t)b * HID + k];

    float pp = 0.f;
    for (int k = tid; k < HID; k += 256)
        pp = fmaf(g_e1_p[(size_t)b * HID + k], W_e2[k], pp);
    sred[tid] = pp;
    __syncthreads();

    // logits: each of 8 warps handles 2 node-type columns
    {
        int warp = tid >> 5, lane = tid & 31;
        int t0 = warp * 2;
        float a0 = 0.f, a1 = 0.f;
        for (int k = lane; k < HID; k += 32) {
            float hv = sh_h[k];
            a0 = fmaf(hv, W_node[k * NT + t0], a0);
            a1 = fmaf(hv, W_node[k * NT + t0 + 1], a1);
        }
        #pragma unroll
        for (int off = 16; off; off >>= 1) {
            a0 += __shfl_down_sync(0xffffffffu, a0, off);
            a1 += __shfl_down_sync(0xffffffffu, a1, off);
        }
        if (lane == 0) {
            sh_logits[t0]     = a0 + b_node[t0];
            sh_logits[t0 + 1] = a1 + b_node[t0 + 1];
        }
    }
    __syncthreads();
    #pragma unroll
    for (int s = 128; s > 0; s >>= 1) {
        if (tid < s) sred[tid] += sred[tid + s];
        __syncthreads();
    }
    if (tid == 0) sh_p = 1.f / (1.f + expf(-(sred[0] + b_e2[0])));
    __syncthreads();

    // node_logits broadcast: [b, N, 16], vectorized float4
    size_t base1 = (size_t)b * N * NT;
    float4 lg[4];
    #pragma unroll
    for (int q = 0; q < 4; q++)
        lg[q] = make_float4(sh_logits[4*q], sh_logits[4*q+1],
                            sh_logits[4*q+2], sh_logits[4*q+3]);
    {
        float4* o4 = reinterpret_cast<float4*>(out + base1);
        int n4 = N * NT / 4;
        for (int i = tid; i < n4; i += 256)
            o4[i] = lg[i & 3];
        // scalar tail if N*NT not divisible by 4 (not expected)
        for (int i = n4 * 4 + tid; i < N * NT; i += 256)
            out[base1 + i] = sh_logits[i & (NT - 1)];
    }

    // edge_probs: p on strict lower triangle (j < i), zeros elsewhere
    if (has_edges) {
        float p = sh_p;
        size_t base2 = (size_t)Bsz * N * NT + (size_t)b * N * N;
        if ((N & 3) == 0) {
            float4* e4 = reinterpret_cast<float4*>(out + base2);
            int nr4 = N >> 2;
            int tot = N * nr4;
            for (int idx = tid; idx < tot; idx += 256) {
                int i  = idx / nr4;
                int j0 = (idx - i * nr4) << 2;
                float4 v;
                v.x = (j0 + 0 < i) ? p : 0.f;
                v.y = (j0 + 1 < i) ? p : 0.f;
                v.z = (j0 + 2 < i) ? p : 0.f;
                v.w = (j0 + 3 < i) ? p : 0.f;
                e4[idx] = v;
            }
        } else {
            for (int idx = tid; idx < N * N; idx += 256) {
                int i = idx / N, j = idx - i * N;
                out[base2 + idx] = (j < i) ? p : 0.f;
            }
        }
    }
}

// ---------------------------------------------------------------------------
// Inputs (metadata order): z, num_nodes, W_z, b_z, W_node, b_node,
//                          W_e1, b_e1, W_e2, b_e2
// num_nodes sits in device memory (can't read under graph capture);
// derive N on host from out_size: per-batch = N*N + 16*N.
// ---------------------------------------------------------------------------
extern "C" void kernel_launch(void* const* d_in, const int* in_sizes, int n_in,
                              void* d_out, int out_size)
{
    const float* z      = (const float*)d_in[0];
    const float* W_z    = (const float*)d_in[2];
    const float* b_z    = (const float*)d_in[3];
    const float* W_node = (const float*)d_in[4];
    const float* b_node = (const float*)d_in[5];
    const float* W_e1   = (const float*)d_in[6];
    const float* b_e1   = (const float*)d_in[7];
    const float* W_e2   = (const float*)d_in[8];
    const float* b_e2   = (const float*)d_in[9];
    float* out = (float*)d_out;

    int Bsz = in_sizes[0] / LATENT;
    long per = (long)out_size / (long)Bsz;

    // Solve N^2 + NT*N = per; fallback to logits-only layout if no int root.
    double disc = (double)NT * NT + 4.0 * (double)per;
    int N = (int)((-(double)NT + sqrt(disc)) * 0.5 + 0.5);
    int has_edges = 1;
    if ((long)N * N + (long)NT * N != per) {
        N = (int)(per / NT);
        has_edges = 0;
    }

    float *gh = nullptr, *ge1 = nullptr;
    cudaGetSymbolAddress((void**)&gh,  g_h);
    cudaGetSymbolAddress((void**)&ge1, g_e1);

    dim3 grid(HID / 64, (Bsz + 31) / 32);

    // h = relu(z @ W_z + b_z)                       [Bsz, 512], K=256
    gemm_tiled<false, true><<<grid, 128>>>(z, W_z, nullptr, b_z, gh,
                                           Bsz, HID, LATENT);
    // e1 = relu(h @ (W_e1_top + W_e1_bot) + b_e1)   [Bsz, 512], K=512
    gemm_tiled<true, true><<<grid, 128>>>(gh, W_e1, W_e1 + (size_t)HID * HID,
                                          b_e1, ge1, Bsz, HID, HID);
    // logits + p + broadcast writes
    finalize_kernel<<<Bsz, 256>>>(gh, ge1, W_node, b_node, W_e2, b_e2,
                                  out, Bsz, N, has_edges);
}